// round 16
// baseline (speedup 1.0000x reference)
#include <cuda_runtime.h>
#include <cuda_bf16.h>
#include <cuda_fp16.h>
#include <math.h>

// Problem constants (fixed by the reference)
#define BATCH 2
#define SEQ   2048
#define DMODEL 1024
#define NHEAD 16
#define HD    64          // head dim
#define QKV_ROW (3*DMODEL)

typedef unsigned int uint32;

// ---- mma / ldmatrix / cp.async wrappers -----------------------------------
__device__ __forceinline__ void ldsm_x4(uint32 r[4], uint32 addr) {
    asm volatile("ldmatrix.sync.aligned.m8n8.x4.shared.b16 {%0,%1,%2,%3}, [%4];"
                 : "=r"(r[0]), "=r"(r[1]), "=r"(r[2]), "=r"(r[3]) : "r"(addr));
}
__device__ __forceinline__ void ldsm_x4_t(uint32 r[4], uint32 addr) {
    asm volatile("ldmatrix.sync.aligned.m8n8.x4.trans.shared.b16 {%0,%1,%2,%3}, [%4];"
                 : "=r"(r[0]), "=r"(r[1]), "=r"(r[2]), "=r"(r[3]) : "r"(addr));
}
__device__ __forceinline__ void mma_f16(float d[4], const uint32 a[4],
                                        uint32 b0, uint32 b1) {
    asm volatile(
        "mma.sync.aligned.m16n8k16.row.col.f32.f16.f16.f32 "
        "{%0,%1,%2,%3}, {%4,%5,%6,%7}, {%8,%9}, {%10,%11,%12,%13};"
        : "=f"(d[0]), "=f"(d[1]), "=f"(d[2]), "=f"(d[3])
        : "r"(a[0]), "r"(a[1]), "r"(a[2]), "r"(a[3]),
          "r"(b0), "r"(b1),
          "f"(d[0]), "f"(d[1]), "f"(d[2]), "f"(d[3]));
}
__device__ __forceinline__ void cp16(uint32 smem_addr, const void* gptr) {
    asm volatile("cp.async.ca.shared.global [%0], [%1], 16;\n"
                 :: "r"(smem_addr), "l"(gptr));
}
__device__ __forceinline__ void cp_commit() {
    asm volatile("cp.async.commit_group;\n");
}
template<int N> __device__ __forceinline__ void cp_wait() {
    asm volatile("cp.async.wait_group %0;\n" :: "n"(N));
}
__device__ __forceinline__ uint32 pack_h2(float x, float y) {
    __half2 h = __floats2half2_rn(x, y);
    return *reinterpret_cast<uint32*>(&h);
}

// Scratch (allocation-free rule: __device__ globals)
__device__ __half g_h16[(size_t)BATCH*SEQ*DMODEL];        // fp16 hidden
__device__ __half g_wa16[(size_t)DMODEL*3*DMODEL];        // fp16 W_attn
__device__ __half g_wp16[(size_t)DMODEL*DMODEL];          // fp16 W_proj
__device__ __half g_at16[(size_t)BATCH*SEQ*DMODEL];       // fp16 attn out
// head-major [B][H][S][HD] fp16: q (pre-scaled 1/8), k, v
#define HEADS_ELEMS ((size_t)BATCH*NHEAD*SEQ*HD)
__device__ __half g_q16[HEADS_ELEMS];
__device__ __half g_k16[HEADS_ELEMS];
__device__ __half g_v16[HEADS_ELEMS];

// ---------------------------------------------------------------------------
// Fused fp32 -> fp16 convert over three arrays (one launch).
// ---------------------------------------------------------------------------
__global__ __launch_bounds__(256)
void conv3_kernel(const float* __restrict__ x0, __half* __restrict__ y0, int n0,
                  const float* __restrict__ x1, __half* __restrict__ y1, int n1,
                  const float* __restrict__ x2, __half* __restrict__ y2, int n2)
{
    int i = (blockIdx.x * 256 + threadIdx.x) * 4;
    const float* x; __half* y;
    if (i < n0)            { x = x0; y = y0; }
    else if (i < n0 + n1)  { i -= n0; x = x1; y = y1; }
    else                   { i -= n0 + n1; if (i >= n2) return; x = x2; y = y2; }
    float4 v = *(const float4*)&x[i];
    *(__half2*)&y[i]     = __floats2half2_rn(v.x, v.y);
    *(__half2*)&y[i + 2] = __floats2half2_rn(v.z, v.w);
}

// ---------------------------------------------------------------------------
// Tensor-core fp16 GEMM (fp32 accumulate), cp.async double buffered, BK=64,
// one barrier per k-tile, REGISTER-PIPELINED fragments (ldsm for ks+1 issued
// before the mma burst for ks -> ldsm latency hidden under mma).
// C[M,N] = A[M,K] @ W[K,N] + bias.
// BM=128, BN=128, 256 threads / 8 warps (4m x 2n), warp tile 32x64.
// MODE 0: bias + fp32 store.  MODE 1: bias, q-scale, fp16 head-major scatter
// to Q/K/V (N = 3*DMODEL).
// smem: A stage 128x9 chunks (18432 B) x2 @0, W stage 64x17 chunks (17408 B)
// x2 @36864.  Total 71680 B.
// ---------------------------------------------------------------------------
#define GEMM_SMEM_BYTES 71680
template<int MODE>
__global__ __launch_bounds__(256, 2)
void gemm_fp16_kernel(const __half* __restrict__ A,
                      const __half* __restrict__ W,
                      const float* __restrict__ bias,
                      float* __restrict__ C,
                      __half* __restrict__ Q16,
                      __half* __restrict__ K16,
                      __half* __restrict__ V16,
                      int M, int N, int K)
{
    extern __shared__ uint4 dsm[];
    uint32 base = (uint32)__cvta_generic_to_shared(dsm);
    const uint32 oW = 36864;
    const uint32 stA = 18432, stW = 17408;

    const int tid  = threadIdx.x;
    const int lane = tid & 31;
    const int wid  = tid >> 5;
    const int warp_m = wid & 3;
    const int warp_n = wid >> 2;
    const int row0 = blockIdx.y * 128;
    const int col0 = blockIdx.x * 128;

    // ldmatrix lane offsets
    const int j  = lane & 7;
    const int q  = lane >> 3;
    const int a_row_off = j + (q & 1) * 8;
    const int a_chk_off = q >> 1;
    uint32 aOff[2];
    #pragma unroll
    for (int ma = 0; ma < 2; ma++) {
        int r = warp_m * 32 + ma * 16 + a_row_off;
        aOff[ma] = (uint32)(r * 9 + a_chk_off) * 16;
    }
    uint32 wOff[4];
    #pragma unroll
    for (int nb = 0; nb < 4; nb++) {
        int k = j + (q & 1) * 8;
        int chk = warp_n * 8 + nb * 2 + (q >> 1);
        wOff[nb] = (uint32)(k * 17 + chk) * 16;
    }

    float acc[2][8][4];
    #pragma unroll
    for (int ma = 0; ma < 2; ma++)
        #pragma unroll
        for (int na = 0; na < 8; na++)
            #pragma unroll
            for (int i = 0; i < 4; i++)
                acc[ma][na][i] = 0.f;

    // loader: coords recomputed per call (saves registers)
    auto load_stage = [&](int s) {
        uint32 bA = base + (uint32)(s & 1) * stA;
        uint32 bW = base + oW + (uint32)(s & 1) * stW;
        int k0 = s * 64;
        #pragma unroll
        for (int t = 0; t < 4; t++) {
            int id = tid + t * 256;
            int ar = id >> 3, ac = id & 7;
            int wr = id >> 4, wc = id & 15;
            cp16(bA + (uint32)(ar * 9 + ac) * 16,
                 &A[(size_t)(row0 + ar) * K + k0 + ac * 8]);
            cp16(bW + (uint32)(wr * 17 + wc) * 16,
                 &W[(size_t)(k0 + wr) * N + col0 + wc * 8]);
        }
        cp_commit();
    };

    const int nkt = K / 64;   // 16
    load_stage(0);

    uint32 af[2][2][4], bf[2][4][4];   // [pipeline buf][frag][regs]

    for (int kt = 0; kt < nkt; kt++) {
        cp_wait<0>();          // stage kt resident
        __syncthreads();       // data visible AND previous buffer drained
        if (kt + 1 < nkt) load_stage(kt + 1);

        uint32 bA = base + (uint32)(kt & 1) * stA;
        uint32 bW = base + oW + (uint32)(kt & 1) * stW;

        // fragment prologue: ks=0 into buf 0
        ldsm_x4(af[0][0], bA + aOff[0]);
        ldsm_x4(af[0][1], bA + aOff[1]);
        #pragma unroll
        for (int nb = 0; nb < 4; nb++)
            ldsm_x4_t(bf[0][nb], bW + wOff[nb]);

        #pragma unroll
        for (int ks = 0; ks < 4; ks++) {
            int cur = ks & 1, nxt = cur ^ 1;
            if (ks < 3) {   // issue next frags BEFORE the mma burst
                ldsm_x4(af[nxt][0], bA + aOff[0] + (ks + 1) * 32);
                ldsm_x4(af[nxt][1], bA + aOff[1] + (ks + 1) * 32);
                #pragma unroll
                for (int nb = 0; nb < 4; nb++)
                    ldsm_x4_t(bf[nxt][nb], bW + wOff[nb] + (ks + 1) * 4352);
            }
            #pragma unroll
            for (int nb = 0; nb < 4; nb++)
                #pragma unroll
                for (int ma = 0; ma < 2; ma++) {
                    mma_f16(acc[ma][2*nb],   af[cur][ma], bf[cur][nb][0], bf[cur][nb][1]);
                    mma_f16(acc[ma][2*nb+1], af[cur][ma], bf[cur][nb][2], bf[cur][nb][3]);
                }
        }
    }

    // ---- epilogue ----
    int r_base = row0 + warp_m * 32 + (lane >> 2);
    int c_base = col0 + warp_n * 64 + (lane & 3) * 2;
    #pragma unroll
    for (int ma = 0; ma < 2; ma++) {
        #pragma unroll
        for (int na = 0; na < 8; na++) {
            int c = c_base + na * 8;
            float bx = bias[c], by = bias[c + 1];
            #pragma unroll
            for (int half_i = 0; half_i < 2; half_i++) {
                int r = r_base + ma * 16 + half_i * 8;
                float vx = acc[ma][na][2 * half_i + 0] + bx;
                float vy = acc[ma][na][2 * half_i + 1] + by;
                if (MODE == 0) {
                    *(float2*)&C[(size_t)r * N + c] = make_float2(vx, vy);
                } else {
                    int arr = c >> 10;               // 0=q 1=k 2=v
                    int hh  = (c >> 6) & 15;
                    int dd  = c & 63;
                    int bb  = r >> 11, ss = r & 2047;
                    size_t dst = (((size_t)(bb * NHEAD + hh)) * SEQ + ss) * HD + dd;
                    if (arr == 0) { vx *= 0.125f; vy *= 0.125f; }
                    __half* p = (arr == 0) ? Q16 : (arr == 1) ? K16 : V16;
                    *(__half2*)&p[dst] = __floats2half2_rn(vx, vy);
                }
            }
        }
    }
}

// ---------------------------------------------------------------------------
// Fully-fp16 MMA causal flash attention (fp32 softmax/accumulators),
// register-pipelined K/V fragment loads.
// BM=128 q rows/block, BN=64 keys/tile, 8 warps (warp = 16 q rows).
// ---------------------------------------------------------------------------
#define ATTN_SMEM_BYTES (2 * 18432)
__global__ __launch_bounds__(256, 2)
void attn_mma_kernel(const __half* __restrict__ Q16,
                     const __half* __restrict__ K16,
                     const __half* __restrict__ V16,
                     __half* __restrict__ O16)
{
    extern __shared__ uint4 dsm[];
    uint32 smem_u = (uint32)__cvta_generic_to_shared(dsm);

    const int tid  = threadIdx.x;
    const int lane = tid & 31;
    const int wq   = tid >> 5;
    const int qt = (int)gridDim.x - 1 - (int)blockIdx.x;
    const int h = blockIdx.y, b = blockIdx.z;
    const int q0 = qt * 128;
    const size_t headoff = ((size_t)(b * NHEAD + h)) * SEQ * HD;

    const int gid = lane >> 2;
    const int tig = lane & 3;
    const int row0 = q0 + wq * 16 + gid;

    // ---- Q fragments straight from global (fp16 pairs) ----
    uint32 qf[4][4];
    {
        const __half* Qb = Q16 + headoff;
        #pragma unroll
        for (int ks = 0; ks < 4; ks++) {
            int kc = ks * 16 + 2 * tig;
            qf[ks][0] = *(const uint32*)&Qb[(size_t)row0 * HD + kc];
            qf[ks][1] = *(const uint32*)&Qb[(size_t)(row0 + 8) * HD + kc];
            qf[ks][2] = *(const uint32*)&Qb[(size_t)row0 * HD + kc + 8];
            qf[ks][3] = *(const uint32*)&Qb[(size_t)(row0 + 8) * HD + kc + 8];
        }
    }

    const uint32 kOffBase = (uint32)((((lane >> 4) << 3) + (lane & 7)) * 144
                                     + ((lane >> 3) & 1) * 16);
    const uint32 vOffBase = (uint32)(((lane & 7) + (((lane >> 3) & 1) << 3)) * 144
                                     + (lane >> 4) * 16);

    float o[8][4];
    #pragma unroll
    for (int t = 0; t < 8; t++)
        #pragma unroll
        for (int i = 0; i < 4; i++) o[t][i] = 0.f;
    float m0 = -INFINITY, m1 = -INFINITY, l0 = 0.f, l1 = 0.f;

    const __half* kvsrc[2] = {K16 + headoff, V16 + headoff};
    const int ntiles = 2 * (qt + 1);

    // tile loader: 2 arrays x 64 rows x 8 chunks = 1024 chunks, 4/thread
    {
        #pragma unroll
        for (int t = 0; t < 4; t++) {
            int id = tid + t * 256;
            int arr = id >> 9;
            int r = (id >> 3) & 63;
            int c = id & 7;
            cp16(smem_u + (uint32)(arr * 9216 + r * 144 + c * 16),
                 kvsrc[arr] + (size_t)r * HD + c * 8);
        }
        cp_commit();
    }

    for (int tt = 0; tt < ntiles; tt++) {
        int kb = tt * 64;
        if (tt + 1 < ntiles) {
            uint32 stn = (uint32)((tt + 1) & 1) * 18432;
            int kbn = kb + 64;
            #pragma unroll
            for (int t = 0; t < 4; t++) {
                int id = tid + t * 256;
                int arr = id >> 9;
                int r = (id >> 3) & 63;
                int c = id & 7;
                cp16(smem_u + stn + (uint32)(arr * 9216 + r * 144 + c * 16),
                     kvsrc[arr] + (size_t)(kbn + r) * HD + c * 8);
            }
            cp_commit();
            cp_wait<1>();
        } else {
            cp_wait<0>();
        }
        __syncthreads();

        uint32 stb = smem_u + (uint32)(tt & 1) * 18432;
        uint32 kbse = stb, vbse = stb + 9216;

        // ---- S = Q K^T (single-term fp16), pipelined kf ----
        float s[8][4];
        #pragma unroll
        for (int t = 0; t < 8; t++)
            #pragma unroll
            for (int i = 0; i < 4; i++) s[t][i] = 0.f;

        {
            uint32 kf[2][4][4];
            #pragma unroll
            for (int g = 0; g < 4; g++)
                ldsm_x4(kf[0][g], kbse + (uint32)(g * 2304) + kOffBase);
            #pragma unroll
            for (int ks = 0; ks < 4; ks++) {
                int cur = ks & 1, nxt = cur ^ 1;
                if (ks < 3) {
                    #pragma unroll
                    for (int g = 0; g < 4; g++)
                        ldsm_x4(kf[nxt][g],
                                kbse + (uint32)(g * 2304 + (ks + 1) * 32) + kOffBase);
                }
                #pragma unroll
                for (int g = 0; g < 4; g++) {
                    mma_f16(s[2*g],   qf[ks], kf[cur][g][0], kf[cur][g][1]);
                    mma_f16(s[2*g+1], qf[ks], kf[cur][g][2], kf[cur][g][3]);
                }
            }
        }

        // ---- causal mask (diagonal tiles only) ----
        if (kb + 63 > q0 + wq * 16) {
            #pragma unroll
            for (int t = 0; t < 8; t++) {
                int key = kb + t * 8 + 2 * tig;
                if (key     > row0)     s[t][0] = -INFINITY;
                if (key + 1 > row0)     s[t][1] = -INFINITY;
                if (key     > row0 + 8) s[t][2] = -INFINITY;
                if (key + 1 > row0 + 8) s[t][3] = -INFINITY;
            }
        }

        // ---- online softmax ----
        float r0 = -INFINITY, r1 = -INFINITY;
        #pragma unroll
        for (int t = 0; t < 8; t++) {
            r0 = fmaxf(r0, fmaxf(s[t][0], s[t][1]));
            r1 = fmaxf(r1, fmaxf(s[t][2], s[t][3]));
        }
        r0 = fmaxf(r0, __shfl_xor_sync(0xffffffffu, r0, 1));
        r0 = fmaxf(r0, __shfl_xor_sync(0xffffffffu, r0, 2));
        r1 = fmaxf(r1, __shfl_xor_sync(0xffffffffu, r1, 1));
        r1 = fmaxf(r1, __shfl_xor_sync(0xffffffffu, r1, 2));
        float mn0 = fmaxf(m0, r0), mn1 = fmaxf(m1, r1);
        float c0 = __expf(m0 - mn0), c1 = __expf(m1 - mn1);
        m0 = mn0; m1 = mn1;
        l0 *= c0;  l1 *= c1;
        #pragma unroll
        for (int t = 0; t < 8; t++) {
            s[t][0] = __expf(s[t][0] - m0);
            s[t][1] = __expf(s[t][1] - m0);
            s[t][2] = __expf(s[t][2] - m1);
            s[t][3] = __expf(s[t][3] - m1);
            l0 += s[t][0] + s[t][1];
            l1 += s[t][2] + s[t][3];
        }
        #pragma unroll
        for (int t = 0; t < 8; t++) {
            o[t][0] *= c0; o[t][1] *= c0;
            o[t][2] *= c1; o[t][3] *= c1;
        }

        // ---- pack P fp16 (C-frag == A-frag identity) ----
        uint32 p16[4][4];
        #pragma unroll
        for (int kk = 0; kk < 4; kk++) {
            p16[kk][0] = pack_h2(s[2*kk][0],   s[2*kk][1]);
            p16[kk][1] = pack_h2(s[2*kk][2],   s[2*kk][3]);
            p16[kk][2] = pack_h2(s[2*kk+1][0], s[2*kk+1][1]);
            p16[kk][3] = pack_h2(s[2*kk+1][2], s[2*kk+1][3]);
        }

        // ---- O += P V (single-term fp16), pipelined v4 ----
        {
            uint32 v4[2][4][4];
            #pragma unroll
            for (int g = 0; g < 4; g++)
                ldsm_x4_t(v4[0][g], vbse + (uint32)(g * 32) + vOffBase);
            #pragma unroll
            for (int kk = 0; kk < 4; kk++) {
                int cur = kk & 1, nxt = cur ^ 1;
                if (kk < 3) {
                    #pragma unroll
                    for (int g = 0; g < 4; g++)
                        ldsm_x4_t(v4[nxt][g],
                                  vbse + (uint32)((kk + 1) * 2304 + g * 32) + vOffBase);
                }
                #pragma unroll
                for (int g = 0; g < 4; g++) {
                    mma_f16(o[2*g],   p16[kk], v4[cur][g][0], v4[cur][g][1]);
                    mma_f16(o[2*g+1], p16[kk], v4[cur][g][2], v4[cur][g][3]);
                }
            }
        }
        __syncthreads();
    }

    // ---- finalize: reduce l across quad, normalize, fp16 store ----
    l0 += __shfl_xor_sync(0xffffffffu, l0, 1);
    l0 += __shfl_xor_sync(0xffffffffu, l0, 2);
    l1 += __shfl_xor_sync(0xffffffffu, l1, 1);
    l1 += __shfl_xor_sync(0xffffffffu, l1, 2);
    float i0 = 1.f / l0, i1 = 1.f / l1;
    #pragma unroll
    for (int t = 0; t < 8; t++) {
        int col = h * HD + t * 8 + 2 * tig;
        size_t d0 = ((size_t)(b * SEQ + row0)) * DMODEL + col;
        size_t d1 = ((size_t)(b * SEQ + row0 + 8)) * DMODEL + col;
        *(__half2*)&O16[d0] = __floats2half2_rn(o[t][0] * i0, o[t][1] * i0);
        *(__half2*)&O16[d1] = __floats2half2_rn(o[t][2] * i1, o[t][3] * i1);
    }
}

// ---------------------------------------------------------------------------
// Launch
// ---------------------------------------------------------------------------
extern "C" void kernel_launch(void* const* d_in, const int* in_sizes, int n_in,
                              void* d_out, int out_size)
{
    const float* hidden = (const float*)d_in[0];   // [B,S,D]
    const float* W_attn = (const float*)d_in[1];   // [D,3D]
    const float* b_attn = (const float*)d_in[2];   // [3D]
    const float* W_proj = (const float*)d_in[3];   // [D,D]
    const float* b_proj = (const float*)d_in[4];   // [D]
    float* out = (float*)d_out;                    // [B,S,D]

    __half *h16, *wa16, *wp16, *at16, *q16, *k16, *v16;
    cudaGetSymbolAddress((void**)&h16,  g_h16);
    cudaGetSymbolAddress((void**)&wa16, g_wa16);
    cudaGetSymbolAddress((void**)&wp16, g_wp16);
    cudaGetSymbolAddress((void**)&at16, g_at16);
    cudaGetSymbolAddress((void**)&q16,  g_q16);
    cudaGetSymbolAddress((void**)&k16,  g_k16);
    cudaGetSymbolAddress((void**)&v16,  g_v16);

    cudaFuncSetAttribute(gemm_fp16_kernel<0>,
                         cudaFuncAttributeMaxDynamicSharedMemorySize,
                         GEMM_SMEM_BYTES);
    cudaFuncSetAttribute(gemm_fp16_kernel<1>,
                         cudaFuncAttributeMaxDynamicSharedMemorySize,
                         GEMM_SMEM_BYTES);
    cudaFuncSetAttribute(attn_mma_kernel,
                         cudaFuncAttributeMaxDynamicSharedMemorySize,
                         ATTN_SMEM_BYTES);

    const int M = BATCH * SEQ;   // 4096

    // 0) fp32 -> fp16 converts (single fused launch)
    {
        int n0 = M * DMODEL;              // 4,194,304
        int n1 = DMODEL * 3 * DMODEL;     // 3,145,728
        int n2 = DMODEL * DMODEL;         // 1,048,576
        int total = n0 + n1 + n2;         // 8,388,608
        conv3_kernel<<<total / 1024, 256>>>(hidden, h16, n0,
                                            W_attn, wa16, n1,
                                            W_proj, wp16, n2);
    }
    // 1) QKV projection (fp16 mma) -> fp16 head-major q(scaled)/k/v
    {
        dim3 grid(3 * DMODEL / 128, M / 128);    // (24, 32)
        gemm_fp16_kernel<1><<<grid, 256, GEMM_SMEM_BYTES>>>(
            h16, wa16, b_attn, nullptr, q16, k16, v16, M, 3 * DMODEL, DMODEL);
    }
    // 2) causal attention (fully fp16 mma) -> fp16 output
    {
        dim3 grid(SEQ / 128, NHEAD, BATCH);      // (16, 16, 2)
        attn_mma_kernel<<<grid, 256, ATTN_SMEM_BYTES>>>(q16, k16, v16, at16);
    }
    // 3) output projection (fp16 mma) -> fp32 out
    {
        dim3 grid(DMODEL / 128, M / 128);        // (8, 32)
        gemm_fp16_kernel<0><<<grid, 256, GEMM_SMEM_BYTES>>>(
            at16, wp16, b_proj, out, nullptr, nullptr, nullptr,
            M, DMODEL, DMODEL);
    }
}